// round 15
// baseline (speedup 1.0000x reference)
#include <cuda_runtime.h>
#include <math_constants.h>

#define N_MAX 30000
#define M_MAX 10000
#define LHALF 4.0f                  // domain [-4,4]^3, coords clamped to edge cells

// Grid A: targets = Ps (sparse, 10k)
#define GA     20
#define NCA    (GA * GA * GA)       // 8000
#define INVHA  2.5f
#define CELLHA 0.4f
// Grid B: targets = P (dense, 30k)
#define GB     32
#define NCB    (GB * GB * GB)       // 32768
#define INVHB  4.0f
#define CELLHB 0.25f

#define NCT      (NCA + NCB)        // 40768 real cells
#define SCAN_T   1024
#define SCAN_NB  40                 // 40*1024 = 40960 padded cells
#define NCT_PAD  (SCAN_NB * SCAN_T)

// Device scratch (zero-init at load; self-cleaning across graph replays).
__device__ unsigned int g_counts[NCT_PAD];     // reset inside scan_kernel
__device__ uint2        g_meta[NCT_PAD];       // (block-local excl prefix, count)
__device__ unsigned int g_blockSum[SCAN_NB];
__device__ unsigned int g_blockOff[SCAN_NB];
__device__ unsigned int g_cursor[NCT_PAD];     // reset by reduce_kernel
__device__ float4       g_sp[N_MAX + M_MAX];   // sorted points, .w = orig index bits
__device__ float        g_term[N_MAX + M_MAX];
#define NB_RED 40
__device__ float g_partials[NB_RED];
__device__ int   g_scan_done = 0;              // arrival counters; self-reset
__device__ int   g_done = 0;

// ---------------------------------------------------------------------------
__device__ __forceinline__ int cellCoordG(float x, float invh, int Gq) {
    int c = (int)floorf((x + LHALF) * invh);
    return min(max(c, 0), Gq - 1);
}
__device__ __forceinline__ int cellA(float x, float y, float z) {
    return (cellCoordG(z, INVHA, GA) * GA + cellCoordG(y, INVHA, GA)) * GA
           + cellCoordG(x, INVHA, GA);
}
__device__ __forceinline__ int cellB(float x, float y, float z) {
    return (cellCoordG(z, INVHB, GB) * GB + cellCoordG(y, INVHB, GB)) * GB
           + cellCoordG(x, INVHB, GB);
}
// cell -> [start,end) in the sorted array (two-level scan reconstruction)
__device__ __forceinline__ uint2 cellRange(int c) {
    const unsigned int off = g_blockOff[c >> 10];
    const uint2 mt = g_meta[c];
    return make_uint2(off + mt.x, off + mt.x + mt.y);
}

// Per-dim 2-cell box choice + exact distance from query to the box faces.
// gx = unclamped grid coord.  Box = [c0, c0+1] cells.  A face lying on the
// grid edge covers the clamped outside region -> bound INF on that side.
__device__ __forceinline__ void boxDim(float gx, int Gq, float h,
                                       int& c0, float& bnd) {
    int c = min(max((int)floorf(gx), 0), Gq - 1);
    int o = (gx - (float)c < 0.5f) ? -1 : 0;
    if (c + o < 0) o = 0;
    if (c + o + 1 > Gq - 1) o = Gq - 2 - c;
    c0 = c + o;
    float blo = (c0 == 0)          ? CUDART_INF_F : (gx - (float)c0) * h;
    float bhi = (c0 + 1 == Gq - 1) ? CUDART_INF_F : ((float)(c0 + 2) - gx) * h;
    bnd = fminf(blo, bhi);
}

// ---------------------------------------------------------------------------
// 1) count points per cell.  Ps -> grid A (slots first), P -> grid B.
// ---------------------------------------------------------------------------
__global__ void count_kernel(const float* __restrict__ P,
                             const float* __restrict__ Ps, int n, int m) {
    int i = blockIdx.x * blockDim.x + threadIdx.x;
    if (i < m) {
        const float* q = Ps + 3 * i;
        atomicAdd(&g_counts[cellA(q[0], q[1], q[2])], 1u);
    } else if (i < m + n) {
        const float* p = P + 3 * (i - m);
        atomicAdd(&g_counts[NCA + cellB(p[0], p[1], p[2])], 1u);
    }
}

// ---------------------------------------------------------------------------
// 2) fused two-level exclusive scan over the padded flat cell array.
// ---------------------------------------------------------------------------
__global__ __launch_bounds__(SCAN_T) void scan_kernel() {
    __shared__ unsigned int ssum[SCAN_T];
    __shared__ bool isLast;
    const int t = threadIdx.x;
    const int c = blockIdx.x * SCAN_T + t;

    const unsigned int cnt = g_counts[c];
    g_counts[c] = 0u;                     // clean for next replay
    ssum[t] = cnt;
    __syncthreads();

    for (int off = 1; off < SCAN_T; off <<= 1) {
        unsigned int v = (t >= off) ? ssum[t - off] : 0u;
        __syncthreads();
        ssum[t] += v;
        __syncthreads();
    }
    g_meta[c] = make_uint2(ssum[t] - cnt, cnt);
    if (t == SCAN_T - 1) g_blockSum[blockIdx.x] = ssum[t];

    if (t == 0) {
        __threadfence();
        isLast = (atomicAdd(&g_scan_done, 1) == (int)gridDim.x - 1);
    }
    __syncthreads();

    if (isLast) {
        __threadfence();
        volatile unsigned int* bs = g_blockSum;
        unsigned int v = (t < SCAN_NB) ? bs[t] : 0u;
        ssum[t] = v;
        __syncthreads();
        for (int off = 1; off < SCAN_NB; off <<= 1) {
            unsigned int w = (t >= off && t < SCAN_NB) ? ssum[t - off] : 0u;
            __syncthreads();
            if (t < SCAN_NB) ssum[t] += w;
            __syncthreads();
        }
        if (t < SCAN_NB) g_blockOff[t] = ssum[t] - v;
        if (t == 0) g_scan_done = 0;
    }
}

// ---------------------------------------------------------------------------
// 3) scatter into sorted slots.  Ps occupy [0,m), P occupy [m,m+n).
// ---------------------------------------------------------------------------
__global__ void scatter_kernel(const float* __restrict__ P,
                               const float* __restrict__ Ps, int n, int m) {
    int i = blockIdx.x * blockDim.x + threadIdx.x;
    if (i < m) {
        float x = Ps[3 * i], y = Ps[3 * i + 1], z = Ps[3 * i + 2];
        int c = cellA(x, y, z);
        unsigned int slot = g_blockOff[c >> 10] + g_meta[c].x +
                            atomicAdd(&g_cursor[c], 1u);
        g_sp[slot] = make_float4(x, y, z, __uint_as_float((unsigned int)i));
    } else if (i < m + n) {
        int j = i - m;
        float x = P[3 * j], y = P[3 * j + 1], z = P[3 * j + 2];
        int c = NCA + cellB(x, y, z);
        unsigned int slot = g_blockOff[c >> 10] + g_meta[c].x +
                            atomicAdd(&g_cursor[c], 1u);
        g_sp[slot] = make_float4(x, y, z, __uint_as_float((unsigned int)j));
    }
}

// ---------------------------------------------------------------------------
// 4) nearest-neighbor query: ONE WARP PER QUERY, 2x2x2 snapped box.
//    w <  m : Ps point, min-only, searches grid B (float path).
//    w >= m : P point, min+argmin, searches grid A (u64 path).
//    4 rows of 2 contiguous cells; ranges prefetched by lanes 0..3.
//    Completeness: best_d <= (exact box-face distance)*0.999, else
//    warp-uniform brute-force of the whole opposing target array.
// ---------------------------------------------------------------------------
__global__ __launch_bounds__(256)
void query_kernel(const float* __restrict__ prob, int n, int m) {
    const int w = (blockIdx.x * blockDim.x + threadIdx.x) >> 5;
    const int lane = threadIdx.x & 31;
    const int total = n + m;
    if (w >= total) return;

    const float4 q = g_sp[w];
    const bool isB = (w < m);

    const int   Gq    = isB ? GB : GA;
    const float invh  = isB ? INVHB : INVHA;
    const float h     = isB ? CELLHB : CELLHA;
    const int   tbase = isB ? NCA : 0;
    const unsigned int bf0 = isB ? (unsigned int)m : 0u;
    const unsigned int bf1 = isB ? (unsigned int)(m + n) : (unsigned int)m;

    // unclamped grid coords
    const float gx = (q.x + LHALF) * invh;
    const float gy = (q.y + LHALF) * invh;
    const float gz = (q.z + LHALF) * invh;

    int cx0, cy0, cz0;
    float bx, by, bz;
    boxDim(gx, Gq, h, cx0, bx);
    boxDim(gy, Gq, h, cy0, by);
    boxDim(gz, Gq, h, cz0, bz);
    const float bnd = fminf(bx, fminf(by, bz)) * 0.999f;
    const float bnd2 = bnd * bnd;           // may be INF*... stays INF

    // ---- prefetch the 4 row ranges via lanes 0..3
    unsigned int rr0 = 0, rr1 = 0;
    if (lane < 4) {
        const int rz = cz0 + (lane >> 1);
        const int ry = cy0 + (lane & 1);
        const int rowb = tbase + (rz * Gq + ry) * Gq + cx0;
        rr0 = cellRange(rowb).x;
        rr1 = cellRange(rowb + 1).y;
    }

    if (isB) {
        // ================= min-only (float) =================
        float best = CUDART_INF_F;
        #pragma unroll
        for (int j = 0; j < 4; j++) {
            const unsigned int r0 = __shfl_sync(0xFFFFFFFFu, rr0, j);
            const unsigned int r1 = __shfl_sync(0xFFFFFFFFu, rr1, j);
            for (unsigned int v = r0 + lane; v < r1; v += 32) {
                const float4 tp = g_sp[v];
                float ddx = q.x - tp.x;
                float ddy = q.y - tp.y;
                float ddz = q.z - tp.z;
                best = fminf(best, fmaf(ddx, ddx, fmaf(ddy, ddy, ddz * ddz)));
            }
        }
        #pragma unroll
        for (int off = 16; off > 0; off >>= 1)
            best = fminf(best, __shfl_xor_sync(0xFFFFFFFFu, best, off));

        if (!(best <= bnd2)) {              // warp-uniform fallback
            for (unsigned int v = bf0 + lane; v < bf1; v += 32) {
                const float4 tp = g_sp[v];
                float ddx = q.x - tp.x;
                float ddy = q.y - tp.y;
                float ddz = q.z - tp.z;
                best = fminf(best, fmaf(ddx, ddx, fmaf(ddy, ddy, ddz * ddz)));
            }
            #pragma unroll
            for (int off = 16; off > 0; off >>= 1)
                best = fminf(best, __shfl_xor_sync(0xFFFFFFFFu, best, off));
        }

        if (lane == 0) {
            const unsigned int qorig = __float_as_uint(q.w);
            g_term[qorig] = sqrtf(best) * __ldg(&prob[qorig]);   // s->o term
        }
    } else {
        // ================= min + argmin (u64 packed) =================
        unsigned long long best = 0xFFFFFFFFFFFFFFFFull;   // (d2_bits<<32)|idx
        #pragma unroll
        for (int j = 0; j < 4; j++) {
            const unsigned int r0 = __shfl_sync(0xFFFFFFFFu, rr0, j);
            const unsigned int r1 = __shfl_sync(0xFFFFFFFFu, rr1, j);
            for (unsigned int v = r0 + lane; v < r1; v += 32) {
                const float4 tp = g_sp[v];
                float ddx = q.x - tp.x;
                float ddy = q.y - tp.y;
                float ddz = q.z - tp.z;
                float d2 = fmaf(ddx, ddx, fmaf(ddy, ddy, ddz * ddz));
                unsigned long long pk =
                    ((unsigned long long)__float_as_uint(d2) << 32) |
                    (unsigned long long)__float_as_uint(tp.w);
                if (pk < best) best = pk;
            }
        }
        #pragma unroll
        for (int off = 16; off > 0; off >>= 1) {
            unsigned long long ob = __shfl_xor_sync(0xFFFFFFFFu, best, off);
            if (ob < best) best = ob;
        }
        float bestd2 = __uint_as_float((unsigned int)(best >> 32));

        if (!(bestd2 <= bnd2)) {            // warp-uniform fallback
            for (unsigned int v = bf0 + lane; v < bf1; v += 32) {
                const float4 tp = g_sp[v];
                float ddx = q.x - tp.x;
                float ddy = q.y - tp.y;
                float ddz = q.z - tp.z;
                float d2 = fmaf(ddx, ddx, fmaf(ddy, ddy, ddz * ddz));
                unsigned long long pk =
                    ((unsigned long long)__float_as_uint(d2) << 32) |
                    (unsigned long long)__float_as_uint(tp.w);
                if (pk < best) best = pk;
            }
            #pragma unroll
            for (int off = 16; off > 0; off >>= 1) {
                unsigned long long ob = __shfl_xor_sync(0xFFFFFFFFu, best, off);
                if (ob < best) best = ob;
            }
        }

        if (lane == 0) {
            const float d = sqrtf(__uint_as_float((unsigned int)(best >> 32)));
            const unsigned int widx = (unsigned int)(best & 0xFFFFFFFFu);
            const unsigned int qorig = __float_as_uint(q.w);
            g_term[m + qorig] = d * __ldg(&prob[widx]);          // o->s term
        }
    }
}

// ---------------------------------------------------------------------------
// 5) deterministic fixed-order sum + fused final; resets cursors for replay.
// ---------------------------------------------------------------------------
__global__ __launch_bounds__(256)
void reduce_kernel(int total, float* __restrict__ out) {
    __shared__ float ssum[256];
    __shared__ bool isLast;
    const int stride = gridDim.x * blockDim.x;
    const int tid0 = blockIdx.x * blockDim.x + threadIdx.x;

    for (int i = tid0; i < NCT_PAD; i += stride) g_cursor[i] = 0u;

    float sum = 0.0f;
    for (int i = tid0; i < total; i += stride)
        sum += g_term[i];

    ssum[threadIdx.x] = sum;
    __syncthreads();
    for (int off = 128; off > 0; off >>= 1) {
        if (threadIdx.x < off) ssum[threadIdx.x] += ssum[threadIdx.x + off];
        __syncthreads();
    }
    if (threadIdx.x == 0) {
        g_partials[blockIdx.x] = ssum[0];
        __threadfence();
        int t = atomicAdd(&g_done, 1);
        isLast = (t == (int)gridDim.x - 1);
    }
    __syncthreads();

    if (isLast) {
        __threadfence();
        volatile float* gp = g_partials;
        float v = (threadIdx.x < (int)gridDim.x) ? gp[threadIdx.x] : 0.0f;
        ssum[threadIdx.x] = v;
        __syncthreads();
        for (int off = 128; off > 0; off >>= 1) {
            if (threadIdx.x < off) ssum[threadIdx.x] += ssum[threadIdx.x + off];
            __syncthreads();
        }
        if (threadIdx.x == 0) {
            out[0] = ssum[0];
            g_done = 0;
        }
    }
}

// ---------------------------------------------------------------------------
// Launch: 5 kernels.
// ---------------------------------------------------------------------------
extern "C" void kernel_launch(void* const* d_in, const int* in_sizes, int n_in,
                              void* d_out, int out_size) {
    const float* P    = (const float*)d_in[0];
    const float* Ps   = (const float*)d_in[1];
    const float* prob = (const float*)d_in[2];
    float* out = (float*)d_out;

    const int n = in_sizes[0] / 3;   // 30000
    const int m = in_sizes[1] / 3;   // 10000
    const int total = n + m;
    const int nb = (total + 255) / 256;

    count_kernel<<<nb, 256>>>(P, Ps, n, m);
    scan_kernel<<<SCAN_NB, SCAN_T>>>();
    scatter_kernel<<<nb, 256>>>(P, Ps, n, m);
    query_kernel<<<(total * 32 + 255) / 256, 256>>>(prob, n, m);
    reduce_kernel<<<NB_RED, 256>>>(total, out);
}

// round 16
// speedup vs baseline: 1.2526x; 1.2526x over previous
#include <cuda_runtime.h>
#include <math_constants.h>

#define N_MAX 30000
#define M_MAX 10000
#define LHALF 4.0f                  // domain [-4,4]^3, coords clamped to edge cells

// Grid A: targets = Ps (sparse, 10k) -> coarser cells
#define GA     24
#define NCA    (GA * GA * GA)       // 13824
#define INVHA  3.0f
#define CELLHA (1.0f / 3.0f)
// Grid B: targets = P (dense, 30k) -> finer cells
#define GB     32
#define NCB    (GB * GB * GB)       // 32768
#define INVHB  4.0f
#define CELLHB 0.25f

#define NCT      (NCA + NCB)        // 46592 real cells
#define SCAN_T   1024
#define SCAN_NB  46                 // 46*1024 = 47104 padded cells
#define NCT_PAD  (SCAN_NB * SCAN_T)

// Device scratch (zero-init at load; self-cleaning across graph replays).
__device__ unsigned int g_counts[NCT_PAD];     // reset inside scan_kernel
__device__ uint2        g_meta[NCT_PAD];       // (block-local excl prefix, count)
__device__ unsigned int g_blockSum[SCAN_NB];
__device__ unsigned int g_blockOff[SCAN_NB];
__device__ unsigned int g_cursor[NCT_PAD];     // reset by reduce_kernel
__device__ float4       g_sp[N_MAX + M_MAX];   // sorted points, .w = orig index bits
__device__ float        g_term[N_MAX + M_MAX];
#define NB_RED 40
__device__ float g_partials[NB_RED];
__device__ int   g_scan_done = 0;              // arrival counters; self-reset
__device__ int   g_done = 0;

// ---------------------------------------------------------------------------
__device__ __forceinline__ int cellCoordG(float x, float invh, int Gq) {
    int c = (int)floorf((x + LHALF) * invh);
    return min(max(c, 0), Gq - 1);
}
__device__ __forceinline__ int cellA(float x, float y, float z) {
    return (cellCoordG(z, INVHA, GA) * GA + cellCoordG(y, INVHA, GA)) * GA
           + cellCoordG(x, INVHA, GA);
}
__device__ __forceinline__ int cellB(float x, float y, float z) {
    return (cellCoordG(z, INVHB, GB) * GB + cellCoordG(y, INVHB, GB)) * GB
           + cellCoordG(x, INVHB, GB);
}
// cell -> [start,end) in the sorted array (two-level scan reconstruction)
__device__ __forceinline__ uint2 cellRange(int c) {
    const unsigned int off = g_blockOff[c >> 10];
    const uint2 mt = g_meta[c];
    return make_uint2(off + mt.x, off + mt.x + mt.y);
}

// ---------------------------------------------------------------------------
// Generic warp box scan: (2r+1)^3 cells around (cx,cy,cz), clamped.  Rows
// (iz,iy) are x-contiguous slot runs; lanes 0..nrows-1 prefetch ranges and
// broadcast via shfl; lanes stride candidates inside each run (coalesced).
// Requires (2r+1)^2 <= 32, i.e. r <= 2.
// ---------------------------------------------------------------------------
__device__ __forceinline__ float warpScanBoxF(
    float4 q, int tbase, int Gq, int cx, int cy, int cz, int r, int lane,
    float best) {
    const int x0 = max(cx - r, 0), x1 = min(cx + r, Gq - 1);
    const int y0 = max(cy - r, 0), y1 = min(cy + r, Gq - 1);
    const int z0 = max(cz - r, 0), z1 = min(cz + r, Gq - 1);
    const int ny = y1 - y0 + 1;
    const int nrows = (z1 - z0 + 1) * ny;

    unsigned int rr0 = 0, rr1 = 0;
    if (lane < nrows) {
        const int rz = lane / ny;
        const int ry = lane - rz * ny;
        const int rowb = tbase + ((z0 + rz) * Gq + (y0 + ry)) * Gq;
        rr0 = cellRange(rowb + x0).x;
        rr1 = cellRange(rowb + x1).y;
    }
    for (int j = 0; j < nrows; j++) {
        const unsigned int r0 = __shfl_sync(0xFFFFFFFFu, rr0, j);
        const unsigned int r1 = __shfl_sync(0xFFFFFFFFu, rr1, j);
        for (unsigned int v = r0 + lane; v < r1; v += 32) {
            const float4 tp = g_sp[v];
            float ddx = q.x - tp.x;
            float ddy = q.y - tp.y;
            float ddz = q.z - tp.z;
            best = fminf(best, fmaf(ddx, ddx, fmaf(ddy, ddy, ddz * ddz)));
        }
    }
    #pragma unroll
    for (int off = 16; off > 0; off >>= 1)
        best = fminf(best, __shfl_xor_sync(0xFFFFFFFFu, best, off));
    return best;
}

__device__ __forceinline__ unsigned long long warpScanBoxU(
    float4 q, int tbase, int Gq, int cx, int cy, int cz, int r, int lane,
    unsigned long long best) {
    const int x0 = max(cx - r, 0), x1 = min(cx + r, Gq - 1);
    const int y0 = max(cy - r, 0), y1 = min(cy + r, Gq - 1);
    const int z0 = max(cz - r, 0), z1 = min(cz + r, Gq - 1);
    const int ny = y1 - y0 + 1;
    const int nrows = (z1 - z0 + 1) * ny;

    unsigned int rr0 = 0, rr1 = 0;
    if (lane < nrows) {
        const int rz = lane / ny;
        const int ry = lane - rz * ny;
        const int rowb = tbase + ((z0 + rz) * Gq + (y0 + ry)) * Gq;
        rr0 = cellRange(rowb + x0).x;
        rr1 = cellRange(rowb + x1).y;
    }
    for (int j = 0; j < nrows; j++) {
        const unsigned int r0 = __shfl_sync(0xFFFFFFFFu, rr0, j);
        const unsigned int r1 = __shfl_sync(0xFFFFFFFFu, rr1, j);
        for (unsigned int v = r0 + lane; v < r1; v += 32) {
            const float4 tp = g_sp[v];
            float ddx = q.x - tp.x;
            float ddy = q.y - tp.y;
            float ddz = q.z - tp.z;
            float d2 = fmaf(ddx, ddx, fmaf(ddy, ddy, ddz * ddz));
            unsigned long long pk =
                ((unsigned long long)__float_as_uint(d2) << 32) |
                (unsigned long long)__float_as_uint(tp.w);
            if (pk < best) best = pk;
        }
    }
    #pragma unroll
    for (int off = 16; off > 0; off >>= 1) {
        unsigned long long ob = __shfl_xor_sync(0xFFFFFFFFu, best, off);
        if (ob < best) best = ob;
    }
    return best;
}

// ---------------------------------------------------------------------------
// 1) count points per cell.  Ps -> grid A (slots first), P -> grid B.
// ---------------------------------------------------------------------------
__global__ void count_kernel(const float* __restrict__ P,
                             const float* __restrict__ Ps, int n, int m) {
    int i = blockIdx.x * blockDim.x + threadIdx.x;
    if (i < m) {
        const float* q = Ps + 3 * i;
        atomicAdd(&g_counts[cellA(q[0], q[1], q[2])], 1u);
    } else if (i < m + n) {
        const float* p = P + 3 * (i - m);
        atomicAdd(&g_counts[NCA + cellB(p[0], p[1], p[2])], 1u);
    }
}

// ---------------------------------------------------------------------------
// 2) fused two-level exclusive scan over the padded flat cell array.
// ---------------------------------------------------------------------------
__global__ __launch_bounds__(SCAN_T) void scan_kernel() {
    __shared__ unsigned int ssum[SCAN_T];
    __shared__ bool isLast;
    const int t = threadIdx.x;
    const int c = blockIdx.x * SCAN_T + t;

    const unsigned int cnt = g_counts[c];
    g_counts[c] = 0u;                     // clean for next replay
    ssum[t] = cnt;
    __syncthreads();

    for (int off = 1; off < SCAN_T; off <<= 1) {
        unsigned int v = (t >= off) ? ssum[t - off] : 0u;
        __syncthreads();
        ssum[t] += v;
        __syncthreads();
    }
    g_meta[c] = make_uint2(ssum[t] - cnt, cnt);
    if (t == SCAN_T - 1) g_blockSum[blockIdx.x] = ssum[t];

    if (t == 0) {
        __threadfence();
        isLast = (atomicAdd(&g_scan_done, 1) == (int)gridDim.x - 1);
    }
    __syncthreads();

    if (isLast) {
        __threadfence();
        volatile unsigned int* bs = g_blockSum;
        unsigned int v = (t < SCAN_NB) ? bs[t] : 0u;
        ssum[t] = v;
        __syncthreads();
        for (int off = 1; off < SCAN_NB; off <<= 1) {
            unsigned int w = (t >= off && t < SCAN_NB) ? ssum[t - off] : 0u;
            __syncthreads();
            if (t < SCAN_NB) ssum[t] += w;
            __syncthreads();
        }
        if (t < SCAN_NB) g_blockOff[t] = ssum[t] - v;
        if (t == 0) g_scan_done = 0;
    }
}

// ---------------------------------------------------------------------------
// 3) scatter into sorted slots.  Ps occupy [0,m), P occupy [m,m+n).
// ---------------------------------------------------------------------------
__global__ void scatter_kernel(const float* __restrict__ P,
                               const float* __restrict__ Ps, int n, int m) {
    int i = blockIdx.x * blockDim.x + threadIdx.x;
    if (i < m) {
        float x = Ps[3 * i], y = Ps[3 * i + 1], z = Ps[3 * i + 2];
        int c = cellA(x, y, z);
        unsigned int slot = g_blockOff[c >> 10] + g_meta[c].x +
                            atomicAdd(&g_cursor[c], 1u);
        g_sp[slot] = make_float4(x, y, z, __uint_as_float((unsigned int)i));
    } else if (i < m + n) {
        int j = i - m;
        float x = P[3 * j], y = P[3 * j + 1], z = P[3 * j + 2];
        int c = NCA + cellB(x, y, z);
        unsigned int slot = g_blockOff[c >> 10] + g_meta[c].x +
                            atomicAdd(&g_cursor[c], 1u);
        g_sp[slot] = make_float4(x, y, z, __uint_as_float((unsigned int)j));
    }
}

// ---------------------------------------------------------------------------
// 4) nearest-neighbor query: ONE WARP PER QUERY, three escalating stages.
//    Stage 1: 3x3x3 box  (complete if best_d <=  h*0.999 - o)
//    Stage 2: 5x5x5 box  (complete if best_d <= 2h*0.999 - o)   [~5% of warps]
//    Stage 3: brute-force scan of whole opposing target array   [~0.1%]
//    All merges exact (float min / u64 packed (d2,idx) min).
// ---------------------------------------------------------------------------
__global__ __launch_bounds__(256)
void query_kernel(const float* __restrict__ prob, int n, int m) {
    const int w = (blockIdx.x * blockDim.x + threadIdx.x) >> 5;
    const int lane = threadIdx.x & 31;
    const int total = n + m;
    if (w >= total) return;

    const float4 q = g_sp[w];
    const bool isB = (w < m);

    const int   Gq    = isB ? GB : GA;
    const float invh  = isB ? INVHB : INVHA;
    const float h     = isB ? CELLHB : CELLHA;
    const int   tbase = isB ? NCA : 0;
    const unsigned int bf0 = isB ? (unsigned int)m : 0u;
    const unsigned int bf1 = isB ? (unsigned int)(m + n) : (unsigned int)m;

    const int cx = cellCoordG(q.x, invh, Gq);
    const int cy = cellCoordG(q.y, invh, Gq);
    const int cz = cellCoordG(q.z, invh, Gq);
    const float o = fmaxf(fmaxf(fabsf(q.x), fmaxf(fabsf(q.y), fabsf(q.z))) - LHALF, 0.0f);
    const float b1 = h * 0.999f - o;            // stage-1 completeness radius
    const float b2 = 2.0f * h * 0.999f - o;     // stage-2 completeness radius

    if (isB) {
        // ================= min-only (float) =================
        float best = warpScanBoxF(q, tbase, Gq, cx, cy, cz, 1, lane,
                                  CUDART_INF_F);
        if (!(b1 > 0.0f && best <= b1 * b1)) {
            best = warpScanBoxF(q, tbase, Gq, cx, cy, cz, 2, lane, best);
            if (!(b2 > 0.0f && best <= b2 * b2)) {
                for (unsigned int v = bf0 + lane; v < bf1; v += 32) {
                    const float4 tp = g_sp[v];
                    float ddx = q.x - tp.x;
                    float ddy = q.y - tp.y;
                    float ddz = q.z - tp.z;
                    best = fminf(best, fmaf(ddx, ddx, fmaf(ddy, ddy, ddz * ddz)));
                }
                #pragma unroll
                for (int off = 16; off > 0; off >>= 1)
                    best = fminf(best, __shfl_xor_sync(0xFFFFFFFFu, best, off));
            }
        }

        if (lane == 0) {
            const unsigned int qorig = __float_as_uint(q.w);
            g_term[qorig] = sqrtf(best) * __ldg(&prob[qorig]);   // s->o term
        }
    } else {
        // ================= min + argmin (u64 packed) =================
        unsigned long long best = warpScanBoxU(q, tbase, Gq, cx, cy, cz, 1,
                                               lane, 0xFFFFFFFFFFFFFFFFull);
        float bestd2 = __uint_as_float((unsigned int)(best >> 32));
        if (!(b1 > 0.0f && bestd2 <= b1 * b1)) {
            best = warpScanBoxU(q, tbase, Gq, cx, cy, cz, 2, lane, best);
            bestd2 = __uint_as_float((unsigned int)(best >> 32));
            if (!(b2 > 0.0f && bestd2 <= b2 * b2)) {
                for (unsigned int v = bf0 + lane; v < bf1; v += 32) {
                    const float4 tp = g_sp[v];
                    float ddx = q.x - tp.x;
                    float ddy = q.y - tp.y;
                    float ddz = q.z - tp.z;
                    float d2 = fmaf(ddx, ddx, fmaf(ddy, ddy, ddz * ddz));
                    unsigned long long pk =
                        ((unsigned long long)__float_as_uint(d2) << 32) |
                        (unsigned long long)__float_as_uint(tp.w);
                    if (pk < best) best = pk;
                }
                #pragma unroll
                for (int off = 16; off > 0; off >>= 1) {
                    unsigned long long ob = __shfl_xor_sync(0xFFFFFFFFu, best, off);
                    if (ob < best) best = ob;
                }
            }
        }

        if (lane == 0) {
            const float d = sqrtf(__uint_as_float((unsigned int)(best >> 32)));
            const unsigned int widx = (unsigned int)(best & 0xFFFFFFFFu);
            const unsigned int qorig = __float_as_uint(q.w);
            g_term[m + qorig] = d * __ldg(&prob[widx]);          // o->s term
        }
    }
}

// ---------------------------------------------------------------------------
// 5) deterministic fixed-order sum + fused final; resets cursors for replay.
// ---------------------------------------------------------------------------
__global__ __launch_bounds__(256)
void reduce_kernel(int total, float* __restrict__ out) {
    __shared__ float ssum[256];
    __shared__ bool isLast;
    const int stride = gridDim.x * blockDim.x;
    const int tid0 = blockIdx.x * blockDim.x + threadIdx.x;

    for (int i = tid0; i < NCT_PAD; i += stride) g_cursor[i] = 0u;

    float sum = 0.0f;
    for (int i = tid0; i < total; i += stride)
        sum += g_term[i];

    ssum[threadIdx.x] = sum;
    __syncthreads();
    for (int off = 128; off > 0; off >>= 1) {
        if (threadIdx.x < off) ssum[threadIdx.x] += ssum[threadIdx.x + off];
        __syncthreads();
    }
    if (threadIdx.x == 0) {
        g_partials[blockIdx.x] = ssum[0];
        __threadfence();
        int t = atomicAdd(&g_done, 1);
        isLast = (t == (int)gridDim.x - 1);
    }
    __syncthreads();

    if (isLast) {
        __threadfence();
        volatile float* gp = g_partials;
        float v = (threadIdx.x < (int)gridDim.x) ? gp[threadIdx.x] : 0.0f;
        ssum[threadIdx.x] = v;
        __syncthreads();
        for (int off = 128; off > 0; off >>= 1) {
            if (threadIdx.x < off) ssum[threadIdx.x] += ssum[threadIdx.x + off];
            __syncthreads();
        }
        if (threadIdx.x == 0) {
            out[0] = ssum[0];
            g_done = 0;
        }
    }
}

// ---------------------------------------------------------------------------
// Launch: 5 kernels.
// ---------------------------------------------------------------------------
extern "C" void kernel_launch(void* const* d_in, const int* in_sizes, int n_in,
                              void* d_out, int out_size) {
    const float* P    = (const float*)d_in[0];
    const float* Ps   = (const float*)d_in[1];
    const float* prob = (const float*)d_in[2];
    float* out = (float*)d_out;

    const int n = in_sizes[0] / 3;   // 30000
    const int m = in_sizes[1] / 3;   // 10000
    const int total = n + m;
    const int nb = (total + 255) / 256;

    count_kernel<<<nb, 256>>>(P, Ps, n, m);
    scan_kernel<<<SCAN_NB, SCAN_T>>>();
    scatter_kernel<<<nb, 256>>>(P, Ps, n, m);
    query_kernel<<<(total * 32 + 255) / 256, 256>>>(prob, n, m);
    reduce_kernel<<<NB_RED, 256>>>(total, out);
}